// round 14
// baseline (speedup 1.0000x reference)
#include <cuda_runtime.h>

#define N_NODES 100000
#define N_EDGES 1600000
#define IN_DIM 64
#define HID_DIM 128
#define OUT_DIM 40
#define CAP 80
#define TILE 128
#define NTILES ((N_NODES + TILE - 1) / TILE)   // 782
#define ASTRIDE 132                 // [c][node] tile stride (128 + 4 pad)

// ---------------- scratch ----------------
__device__ __align__(16) float g_agg1[N_NODES * IN_DIM];
__device__ __align__(16) float g_t[N_NODES * OUT_DIM];
__device__ int g_deg[N_NODES];
__device__ int g_csr[N_NODES * CAP];
__device__ int g_is64;

typedef unsigned long long ull;
__device__ __forceinline__ ull f2pack(float lo, float hi) {
    ull r; asm("mov.b64 %0, {%1,%2};" : "=l"(r) : "f"(lo), "f"(hi)); return r;
}
__device__ __forceinline__ void f2unpack(ull v, float& lo, float& hi) {
    asm("mov.b64 {%0,%1}, %2;" : "=f"(lo), "=f"(hi) : "l"(v));
}
__device__ __forceinline__ ull fma2(ull a, ull b, ull c) {
    ull d; asm("fma.rn.f32x2 %0, %1, %2, %3;" : "=l"(d)
               : "l"(a), "l"(b), "l"(c)); return d;
}

// ---------------- K-prep ----------------
__global__ void k_prep(const long long* __restrict__ ei) {
    int i = blockIdx.x * blockDim.x + threadIdx.x;
    if (i < N_NODES) g_deg[i] = 0;
    if (blockIdx.x == 0) {
        long long v = ei[threadIdx.x];
        int ok = (v >= 0 && v < N_NODES);
        int all = __syncthreads_and(ok);
        if (threadIdx.x == 0) g_is64 = all;
    }
}

// ---------------- K-build ----------------
__global__ void k_build(const void* __restrict__ ei) {
    int e = blockIdx.x * blockDim.x + threadIdx.x;
    if (e >= N_EDGES) return;
    int s, d;
    if (g_is64) {
        s = (int)((const long long*)ei)[e];
        d = (int)((const long long*)ei)[N_EDGES + e];
    } else {
        s = ((const int*)ei)[e];
        d = ((const int*)ei)[N_EDGES + e];
    }
    int slot = atomicAdd(&g_deg[d], 1);
    if (slot < CAP) g_csr[d * CAP + slot] = s;
}

// ---------------- K-gather1 ----------------
__global__ void k_gather1(const float* __restrict__ x) {
    int w = (blockIdx.x * blockDim.x + threadIdx.x) >> 5;
    if (w >= N_NODES) return;
    int lane = threadIdx.x & 31;
    int p = lane >> 4;
    int c = lane & 15;
    int deg = min(g_deg[w], CAP);
    const int* row = g_csr + (size_t)w * CAP;

    float4 acc = make_float4(0.f, 0.f, 0.f, 0.f);
    if (p == 0)
        acc = *reinterpret_cast<const float4*>(x + (size_t)w * IN_DIM + c * 4);

    #pragma unroll 4
    for (int j = 0; j < deg; j += 2) {
        if (j + p < deg) {
            int s = row[j + p];
            float4 v = *reinterpret_cast<const float4*>(
                x + (size_t)s * IN_DIM + c * 4);
            acc.x += v.x; acc.y += v.y; acc.z += v.z; acc.w += v.w;
        }
    }
    acc.x += __shfl_xor_sync(0xffffffffu, acc.x, 16);
    acc.y += __shfl_xor_sync(0xffffffffu, acc.y, 16);
    acc.z += __shfl_xor_sync(0xffffffffu, acc.z, 16);
    acc.w += __shfl_xor_sync(0xffffffffu, acc.w, 16);
    if (p == 0)
        *reinterpret_cast<float4*>(g_agg1 + (size_t)w * IN_DIM + c * 4) = acc;
}

// ---------------- K2: fused MLP — coalesced weights + 1024 threads ----------
// Node group ng = tid>>6 (8 nodes, warp-uniform); cols c0 = tid&63, c1 = c0+64.
// Weight reads warp-contiguous (1 wf each); act reads warp-broadcast.
constexpr int S_W2 = 0;                          // [k][c] 128*128 = 16384
constexpr int S_W3 = S_W2 + HID_DIM * HID_DIM;   // [k][c] 128*40  = 5120
constexpr int S_B1 = S_W3 + HID_DIM * OUT_DIM;   // 128
constexpr int S_B2 = S_B1 + HID_DIM;             // 128
constexpr int S_T  = S_B2 + HID_DIM;             // [c][n] 128*132 = 16896
constexpr int S_H  = S_T + HID_DIM * ASTRIDE;    // [c][n] 128*132 = 16896
constexpr int S_A  = S_H;                        // alias (64*132 <= H)
constexpr int S_TOTAL = S_H + HID_DIM * ASTRIDE; // 55552 floats
constexpr int SMEM_BYTES = S_TOTAL * 4;          // 222208 B

__global__ void __launch_bounds__(1024, 1)
k_mlp(const float* __restrict__ W1, const float* __restrict__ b1,
      const float* __restrict__ W2, const float* __restrict__ b2,
      const float* __restrict__ W3) {
    extern __shared__ float sm[];
    int tid = threadIdx.x;

    for (int i = tid; i < HID_DIM * HID_DIM; i += 1024) sm[S_W2 + i] = W2[i];
    for (int i = tid; i < HID_DIM * OUT_DIM; i += 1024) sm[S_W3 + i] = W3[i];
    if (tid < HID_DIM) { sm[S_B1 + tid] = b1[tid]; sm[S_B2 + tid] = b2[tid]; }

    const int c0 = tid & 63;           // first col; second is c0+64
    const int nb = (tid >> 6) * 8;     // node base, warp-uniform (0..120)
    // proj mapping: 16 groups x 64 threads; col = tid&63 (<40 active)
    const int pnb = (tid >> 6) * 8;
    const int pc  = tid & 63;
    const bool pact = pc < OUT_DIM;

    // stage tile 0 into A (transposed [k][n])
    int g = blockIdx.x;
    for (int it = tid; it < 2048; it += 1024) {
        int n = it >> 4, k4 = (it & 15) * 4;
        int node = g * TILE + n;
        float4 v = (node < N_NODES)
            ? *reinterpret_cast<const float4*>(g_agg1 + (size_t)node * IN_DIM + k4)
            : make_float4(0.f, 0.f, 0.f, 0.f);
        sm[S_A + (k4 + 0) * ASTRIDE + n] = v.x;
        sm[S_A + (k4 + 1) * ASTRIDE + n] = v.y;
        sm[S_A + (k4 + 2) * ASTRIDE + n] = v.z;
        sm[S_A + (k4 + 3) * ASTRIDE + n] = v.w;
    }

    for (; g < NTILES; g += gridDim.x) {
        int base = g * TILE;
        __syncthreads();                       // A + weights ready

        // ---- layer 1: 64 -> 128, relu. 2 cols x 8 nodes per thread. ------
        {
            ull acc[2][4];
            {
                float bv0 = sm[S_B1 + c0], bv1 = sm[S_B1 + c0 + 64];
                ull b0 = f2pack(bv0, bv0), b1v = f2pack(bv1, bv1);
                acc[0][0] = b0; acc[0][1] = b0; acc[0][2] = b0; acc[0][3] = b0;
                acc[1][0] = b1v; acc[1][1] = b1v; acc[1][2] = b1v; acc[1][3] = b1v;
            }
            for (int k = 0; k < IN_DIM; k += 2) {
                #pragma unroll
                for (int kk = 0; kk < 2; kk++) {
                    const float* wr = W1 + (k + kk) * HID_DIM + c0;
                    float w0 = __ldg(wr), w1 = __ldg(wr + 64);
                    ulonglong2 p0 = *reinterpret_cast<const ulonglong2*>(
                        &sm[S_A + (k + kk) * ASTRIDE + nb]);
                    ulonglong2 p1 = *reinterpret_cast<const ulonglong2*>(
                        &sm[S_A + (k + kk) * ASTRIDE + nb + 4]);
                    ull wp0 = f2pack(w0, w0), wp1 = f2pack(w1, w1);
                    acc[0][0] = fma2(wp0, p0.x, acc[0][0]);
                    acc[0][1] = fma2(wp0, p0.y, acc[0][1]);
                    acc[0][2] = fma2(wp0, p1.x, acc[0][2]);
                    acc[0][3] = fma2(wp0, p1.y, acc[0][3]);
                    acc[1][0] = fma2(wp1, p0.x, acc[1][0]);
                    acc[1][1] = fma2(wp1, p0.y, acc[1][1]);
                    acc[1][2] = fma2(wp1, p1.x, acc[1][2]);
                    acc[1][3] = fma2(wp1, p1.y, acc[1][3]);
                }
            }
            #pragma unroll
            for (int j = 0; j < 2; j++) {
                int c = c0 + 64 * j;
                float t0,t1,t2,t3,t4,t5,t6,t7;
                f2unpack(acc[j][0],t0,t1); f2unpack(acc[j][1],t2,t3);
                f2unpack(acc[j][2],t4,t5); f2unpack(acc[j][3],t6,t7);
                *reinterpret_cast<float4*>(&sm[S_T + c * ASTRIDE + nb]) =
                    make_float4(fmaxf(t0,0.f), fmaxf(t1,0.f), fmaxf(t2,0.f), fmaxf(t3,0.f));
                *reinterpret_cast<float4*>(&sm[S_T + c * ASTRIDE + nb + 4]) =
                    make_float4(fmaxf(t4,0.f), fmaxf(t5,0.f), fmaxf(t6,0.f), fmaxf(t7,0.f));
            }
        }
        __syncthreads();                       // T ready (A dead)

        // ---- layer 2: 128 -> 128, relu; writes H (clobbers A) ------------
        {
            ull acc[2][4];
            {
                float bv0 = sm[S_B2 + c0], bv1 = sm[S_B2 + c0 + 64];
                ull b0 = f2pack(bv0, bv0), b1v = f2pack(bv1, bv1);
                acc[0][0] = b0; acc[0][1] = b0; acc[0][2] = b0; acc[0][3] = b0;
                acc[1][0] = b1v; acc[1][1] = b1v; acc[1][2] = b1v; acc[1][3] = b1v;
            }
            for (int k = 0; k < HID_DIM; k += 2) {
                #pragma unroll
                for (int kk = 0; kk < 2; kk++) {
                    const float* wr = &sm[S_W2 + (k + kk) * HID_DIM + c0];
                    float w0 = wr[0], w1 = wr[64];
                    ulonglong2 p0 = *reinterpret_cast<const ulonglong2*>(
                        &sm[S_T + (k + kk) * ASTRIDE + nb]);
                    ulonglong2 p1 = *reinterpret_cast<const ulonglong2*>(
                        &sm[S_T + (k + kk) * ASTRIDE + nb + 4]);
                    ull wp0 = f2pack(w0, w0), wp1 = f2pack(w1, w1);
                    acc[0][0] = fma2(wp0, p0.x, acc[0][0]);
                    acc[0][1] = fma2(wp0, p0.y, acc[0][1]);
                    acc[0][2] = fma2(wp0, p1.x, acc[0][2]);
                    acc[0][3] = fma2(wp0, p1.y, acc[0][3]);
                    acc[1][0] = fma2(wp1, p0.x, acc[1][0]);
                    acc[1][1] = fma2(wp1, p0.y, acc[1][1]);
                    acc[1][2] = fma2(wp1, p1.x, acc[1][2]);
                    acc[1][3] = fma2(wp1, p1.y, acc[1][3]);
                }
            }
            #pragma unroll
            for (int j = 0; j < 2; j++) {
                int c = c0 + 64 * j;
                float t0,t1,t2,t3,t4,t5,t6,t7;
                f2unpack(acc[j][0],t0,t1); f2unpack(acc[j][1],t2,t3);
                f2unpack(acc[j][2],t4,t5); f2unpack(acc[j][3],t6,t7);
                *reinterpret_cast<float4*>(&sm[S_H + c * ASTRIDE + nb]) =
                    make_float4(fmaxf(t0,0.f), fmaxf(t1,0.f), fmaxf(t2,0.f), fmaxf(t3,0.f));
                *reinterpret_cast<float4*>(&sm[S_H + c * ASTRIDE + nb + 4]) =
                    make_float4(fmaxf(t4,0.f), fmaxf(t5,0.f), fmaxf(t6,0.f), fmaxf(t7,0.f));
            }
        }
        __syncthreads();                       // H ready

        // ---- projection: 1 col x 8 nodes per thread (640 active) ---------
        if (pact) {
            ull q[4];
            #pragma unroll
            for (int i = 0; i < 4; i++) q[i] = f2pack(0.f, 0.f);
            for (int k = 0; k < HID_DIM; k++) {
                float w = sm[S_W3 + k * OUT_DIM + pc];
                ull wp = f2pack(w, w);
                const float* hr = &sm[S_H + k * ASTRIDE + pnb];
                ulonglong2 p0 = *reinterpret_cast<const ulonglong2*>(hr);
                ulonglong2 p1 = *reinterpret_cast<const ulonglong2*>(hr + 4);
                q[0] = fma2(wp, p0.x, q[0]); q[1] = fma2(wp, p0.y, q[1]);
                q[2] = fma2(wp, p1.x, q[2]); q[3] = fma2(wp, p1.y, q[3]);
            }
            int n0 = base + pnb;
            #pragma unroll
            for (int i = 0; i < 4; i++) {
                float lo, hi;
                f2unpack(q[i], lo, hi);
                int na = n0 + 2 * i, nbx = n0 + 2 * i + 1;
                if (na < N_NODES)  g_t[(size_t)na  * OUT_DIM + pc] = lo;
                if (nbx < N_NODES) g_t[(size_t)nbx * OUT_DIM + pc] = hi;
            }
        }
        __syncthreads();                       // proj done before A clobbers H

        // ---- stage next tile into A -------------------------------------
        int gn = g + gridDim.x;
        if (gn < NTILES) {
            for (int it = tid; it < 2048; it += 1024) {
                int n = it >> 4, k4 = (it & 15) * 4;
                int node = gn * TILE + n;
                float4 v = (node < N_NODES)
                    ? *reinterpret_cast<const float4*>(g_agg1 + (size_t)node * IN_DIM + k4)
                    : make_float4(0.f, 0.f, 0.f, 0.f);
                sm[S_A + (k4 + 0) * ASTRIDE + n] = v.x;
                sm[S_A + (k4 + 1) * ASTRIDE + n] = v.y;
                sm[S_A + (k4 + 2) * ASTRIDE + n] = v.z;
                sm[S_A + (k4 + 3) * ASTRIDE + n] = v.w;
            }
        }
    }
}

// ---------------- K-final2: gather2 + bias + relu + log_softmax -------------
__global__ void k_final2(const float* __restrict__ b3, float* __restrict__ out) {
    int w = (blockIdx.x * blockDim.x + threadIdx.x) >> 5;
    if (w >= N_NODES) return;
    int lane = threadIdx.x & 31;
    int p = lane / 10;
    int c = lane - p * 10;
    bool active = p < 3;
    int deg = min(g_deg[w], CAP);
    const int* row = g_csr + (size_t)w * CAP;

    float4 acc = make_float4(0.f, 0.f, 0.f, 0.f);
    if (p == 0)
        acc = *reinterpret_cast<const float4*>(g_t + (size_t)w * OUT_DIM + c * 4);

    #pragma unroll 3
    for (int j = 0; j < deg; j += 3) {
        if (active && j + p < deg) {
            int s = row[j + p];
            float4 v = *reinterpret_cast<const float4*>(
                g_t + (size_t)s * OUT_DIM + c * 4);
            acc.x += v.x; acc.y += v.y; acc.z += v.z; acc.w += v.w;
        }
    }

    float4 u;
    u.x = acc.x + __shfl_sync(0xffffffffu, acc.x, lane + 10)
                + __shfl_sync(0xffffffffu, acc.x, lane + 20);
    u.y = acc.y + __shfl_sync(0xffffffffu, acc.y, lane + 10)
                + __shfl_sync(0xffffffffu, acc.y, lane + 20);
    u.z = acc.z + __shfl_sync(0xffffffffu, acc.z, lane + 10)
                + __shfl_sync(0xffffffffu, acc.z, lane + 20);
    u.w = acc.w + __shfl_sync(0xffffffffu, acc.w, lane + 10)
                + __shfl_sync(0xffffffffu, acc.w, lane + 20);

    bool owner = lane < 10;
    float4 a = make_float4(-3.4e38f, -3.4e38f, -3.4e38f, -3.4e38f);
    if (owner) {
        float4 bv = *reinterpret_cast<const float4*>(b3 + c * 4);
        a.x = fmaxf(u.x + bv.x, 0.f);
        a.y = fmaxf(u.y + bv.y, 0.f);
        a.z = fmaxf(u.z + bv.z, 0.f);
        a.w = fmaxf(u.w + bv.w, 0.f);
    }

    float m = fmaxf(fmaxf(a.x, a.y), fmaxf(a.z, a.w));
    #pragma unroll
    for (int o = 16; o > 0; o >>= 1)
        m = fmaxf(m, __shfl_xor_sync(0xffffffffu, m, o));

    float s = owner ? (expf(a.x - m) + expf(a.y - m) +
                       expf(a.z - m) + expf(a.w - m)) : 0.f;
    #pragma unroll
    for (int o = 16; o > 0; o >>= 1)
        s += __shfl_xor_sync(0xffffffffu, s, o);

    float lse = m + logf(s);
    if (owner) {
        float4 r = make_float4(a.x - lse, a.y - lse, a.z - lse, a.w - lse);
        *reinterpret_cast<float4*>(out + (size_t)w * OUT_DIM + c * 4) = r;
    }
}

// ---------------- launch ----------------
extern "C" void kernel_launch(void* const* d_in, const int* in_sizes, int n_in,
                              void* d_out, int out_size) {
    const float* x  = (const float*)d_in[0];
    const void*  ei = d_in[1];
    const float* W1 = (const float*)d_in[2];
    const float* b1 = (const float*)d_in[3];
    const float* W2 = (const float*)d_in[4];
    const float* b2 = (const float*)d_in[5];
    const float* W3 = (const float*)d_in[6];
    const float* b3 = (const float*)d_in[7];
    float* out = (float*)d_out;

    static bool attr_set = false;
    if (!attr_set) {
        cudaFuncSetAttribute(k_mlp, cudaFuncAttributeMaxDynamicSharedMemorySize,
                             SMEM_BYTES);
        attr_set = true;
    }

    k_prep<<<(N_NODES + 255) / 256, 256>>>((const long long*)ei);
    k_build<<<(N_EDGES + 255) / 256, 256>>>(ei);
    k_gather1<<<(N_NODES * 32 + 255) / 256, 256>>>(x);
    k_mlp<<<148, 1024, SMEM_BYTES>>>(W1, b1, W2, b2, W3);
    k_final2<<<(N_NODES * 32 + 255) / 256, 256>>>(b3, out);
}

// round 16
// speedup vs baseline: 1.6061x; 1.6061x over previous
#include <cuda_runtime.h>
#include <cuda_bf16.h>
#include <cstdint>

#define N_NODES 100000
#define N_EDGES 1600000
#define IN_DIM 64
#define HID_DIM 128
#define OUT_DIM 40
#define CAP 80
#define TILE 64
#define NTILES ((N_NODES + TILE - 1) / TILE)   // 1563

// ---------------- scratch ----------------
__device__ __align__(16) float g_agg1[N_NODES * IN_DIM];
__device__ __align__(16) float g_t[N_NODES * OUT_DIM];
__device__ int g_deg[N_NODES];
__device__ int g_csr[N_NODES * CAP];
__device__ int g_is64;

// ---------------- helpers ----------------
__device__ __forceinline__ uint32_t smem_u32(const void* p) {
    uint32_t a;
    asm("{ .reg .u64 t; cvta.to.shared.u64 t, %1; cvt.u32.u64 %0, t; }"
        : "=r"(a) : "l"(p));
    return a;
}
__device__ __forceinline__ void ldsm4(uint32_t* r, uint32_t a) {
    asm volatile("ldmatrix.sync.aligned.m8n8.x4.shared.b16 {%0,%1,%2,%3}, [%4];"
                 : "=r"(r[0]), "=r"(r[1]), "=r"(r[2]), "=r"(r[3]) : "r"(a));
}
__device__ __forceinline__ void mma16816(float* c, const uint32_t* a,
                                         const uint32_t* b) {
    asm volatile("mma.sync.aligned.m16n8k16.row.col.f32.bf16.bf16.f32 "
        "{%0,%1,%2,%3}, {%4,%5,%6,%7}, {%8,%9}, {%0,%1,%2,%3};"
        : "+f"(c[0]), "+f"(c[1]), "+f"(c[2]), "+f"(c[3])
        : "r"(a[0]), "r"(a[1]), "r"(a[2]), "r"(a[3]), "r"(b[0]), "r"(b[1]));
}
// pack two floats to bf16x2, low half = e0
__device__ __forceinline__ uint32_t pack_bf16(float e0, float e1) {
    uint32_t r;
    asm("cvt.rn.bf16x2.f32 %0, %1, %2;" : "=r"(r) : "f"(e1), "f"(e0));
    return r;
}

// SMEM layout (bytes). Strides in bf16 elements: A/W1 = 72, others = 136.
constexpr int SM_W1H = 0;                    // 128*72*2  = 18432
constexpr int SM_W1L = 18432;
constexpr int SM_W2H = 36864;                // 128*136*2 = 34816
constexpr int SM_W2L = 71680;
constexpr int SM_W3H = 106496;               // 64*136*2  = 17408 (cols padded)
constexpr int SM_W3L = 123904;
constexpr int SM_TH  = 141312;               // 64*136*2
constexpr int SM_TL  = 158720;
constexpr int SM_HH  = 176128;               // 64*136*2
constexpr int SM_HL  = 193536;
constexpr int SM_AH  = SM_HH;                // alias: A (64*72*2=9216) in H
constexpr int SM_AL  = SM_HL;
constexpr int SM_B1f = 210944;               // 128 floats
constexpr int SM_B2f = 211456;
constexpr int SMEM_MLP = 211968;

// ---------------- K-prep ----------------
__global__ void k_prep(const long long* __restrict__ ei) {
    int i = blockIdx.x * blockDim.x + threadIdx.x;
    if (i < N_NODES) g_deg[i] = 0;
    if (blockIdx.x == 0) {
        long long v = ei[threadIdx.x];
        int ok = (v >= 0 && v < N_NODES);
        int all = __syncthreads_and(ok);
        if (threadIdx.x == 0) g_is64 = all;
    }
}

// ---------------- K-build ----------------
__global__ void k_build(const void* __restrict__ ei) {
    int e = blockIdx.x * blockDim.x + threadIdx.x;
    if (e >= N_EDGES) return;
    int s, d;
    if (g_is64) {
        s = (int)((const long long*)ei)[e];
        d = (int)((const long long*)ei)[N_EDGES + e];
    } else {
        s = ((const int*)ei)[e];
        d = ((const int*)ei)[N_EDGES + e];
    }
    int slot = atomicAdd(&g_deg[d], 1);
    if (slot < CAP) g_csr[d * CAP + slot] = s;
}

// ---------------- K-gather1 ----------------
__global__ void k_gather1(const float* __restrict__ x) {
    int w = (blockIdx.x * blockDim.x + threadIdx.x) >> 5;
    if (w >= N_NODES) return;
    int lane = threadIdx.x & 31;
    int p = lane >> 4;
    int c = lane & 15;
    int deg = min(g_deg[w], CAP);
    const int* row = g_csr + (size_t)w * CAP;

    float4 acc = make_float4(0.f, 0.f, 0.f, 0.f);
    if (p == 0)
        acc = *reinterpret_cast<const float4*>(x + (size_t)w * IN_DIM + c * 4);

    #pragma unroll 4
    for (int j = 0; j < deg; j += 2) {
        if (j + p < deg) {
            int s = row[j + p];
            float4 v = *reinterpret_cast<const float4*>(
                x + (size_t)s * IN_DIM + c * 4);
            acc.x += v.x; acc.y += v.y; acc.z += v.z; acc.w += v.w;
        }
    }
    acc.x += __shfl_xor_sync(0xffffffffu, acc.x, 16);
    acc.y += __shfl_xor_sync(0xffffffffu, acc.y, 16);
    acc.z += __shfl_xor_sync(0xffffffffu, acc.z, 16);
    acc.w += __shfl_xor_sync(0xffffffffu, acc.w, 16);
    if (p == 0)
        *reinterpret_cast<float4*>(g_agg1 + (size_t)w * IN_DIM + c * 4) = acc;
}

// ---------------- K2: HMMA (mma.sync bf16 split) fused MLP -------------------
// D[m=node][n=col] = Act[m][k] * Wt[n][k]; 3-pass split: AhWh + AhWl + AlWh.
__global__ void __launch_bounds__(512, 1)
k_mlp(const float* __restrict__ W1, const float* __restrict__ b1,
      const float* __restrict__ W2, const float* __restrict__ b2,
      const float* __restrict__ W3) {
    extern __shared__ char smem[];
    uint32_t sb = smem_u32(smem);
    float* smf = reinterpret_cast<float*>(smem);
    int tid = threadIdx.x;
    int lane = tid & 31;
    int w = tid >> 5;                  // 0..15
    int wm = w & 3;                    // m group (16 rows)
    int wn = w >> 2;                   // n group

    // ---- zero W3 pad (both hi+lo regions contiguous) ----
    for (int i = tid; i < (SM_TH - SM_W3H) / 4; i += 512)
        reinterpret_cast<uint32_t*>(smem + SM_W3H)[i] = 0;
    __syncthreads();

    // ---- stage weights transposed [c][k], split hi/lo ----
    for (int i = tid; i < IN_DIM * HID_DIM; i += 512) {
        int k = i >> 7, c = i & 127;
        float v = W1[i];
        __nv_bfloat16 h = __float2bfloat16_rn(v);
        __nv_bfloat16 l = __float2bfloat16_rn(v - __bfloat162float(h));
        uint32_t off = (uint32_t)(c * 72 + k) * 2;
        *reinterpret_cast<__nv_bfloat16*>(smem + SM_W1H + off) = h;
        *reinterpret_cast<__nv_bfloat16*>(smem + SM_W1L + off) = l;
    }
    for (int i = tid; i < HID_DIM * HID_DIM; i += 512) {
        int k = i >> 7, c = i & 127;
        float v = W2[i];
        __nv_bfloat16 h = __float2bfloat16_rn(v);
        __nv_bfloat16 l = __float2bfloat16_rn(v - __bfloat162float(h));
        uint32_t off = (uint32_t)(c * 136 + k) * 2;
        *reinterpret_cast<__nv_bfloat16*>(smem + SM_W2H + off) = h;
        *reinterpret_cast<__nv_bfloat16*>(smem + SM_W2L + off) = l;
    }
    for (int i = tid; i < HID_DIM * OUT_DIM; i += 512) {
        int k = i / OUT_DIM, c = i % OUT_DIM;
        float v = W3[i];
        __nv_bfloat16 h = __float2bfloat16_rn(v);
        __nv_bfloat16 l = __float2bfloat16_rn(v - __bfloat162float(h));
        uint32_t off = (uint32_t)(c * 136 + k) * 2;
        *reinterpret_cast<__nv_bfloat16*>(smem + SM_W3H + off) = h;
        *reinterpret_cast<__nv_bfloat16*>(smem + SM_W3L + off) = l;
    }
    if (tid < HID_DIM) {
        smf[SM_B1f / 4 + tid] = b1[tid];
        smf[SM_B2f / 4 + tid] = b2[tid];
    }
    __syncthreads();

    const int arow = lane & 15, acol8 = (lane >> 4) << 3;        // A-frag addr
    const int brow = (lane & 7) + ((lane >> 4) << 3);            // B-frag addr
    const int bcol8 = ((lane >> 3) & 1) << 3;
    const int row0 = lane >> 2, col0 = (lane & 3) * 2;           // C layout

    for (int g = blockIdx.x; g < NTILES; g += gridDim.x) {
        int base = g * TILE;

        // ---- stage A: split-bf16 [node][k], stride 72 ----
        {
            int node = tid >> 3;
            int k8 = (tid & 7) * 8;
            float f[8];
            if (base + node < N_NODES) {
                const float4* p = reinterpret_cast<const float4*>(
                    g_agg1 + (size_t)(base + node) * IN_DIM + k8);
                float4 v0 = p[0], v1 = p[1];
                f[0]=v0.x; f[1]=v0.y; f[2]=v0.z; f[3]=v0.w;
                f[4]=v1.x; f[5]=v1.y; f[6]=v1.z; f[7]=v1.w;
            } else {
                #pragma unroll
                for (int q = 0; q < 8; q++) f[q] = 0.f;
            }
            #pragma unroll
            for (int j = 0; j < 4; j++) {
                uint32_t h2 = pack_bf16(f[2*j], f[2*j+1]);
                float h0 = __uint_as_float(h2 << 16);
                float h1 = __uint_as_float(h2 & 0xFFFF0000u);
                uint32_t l2 = pack_bf16(f[2*j] - h0, f[2*j+1] - h1);
                uint32_t off = (uint32_t)(node * 72 + k8 + 2*j) * 2;
                *reinterpret_cast<uint32_t*>(smem + SM_AH + off) = h2;
                *reinterpret_cast<uint32_t*>(smem + SM_AL + off) = l2;
            }
        }
        __syncthreads();

        // ---- layer 1: 64x128 = A[64x64] @ W1t[128x64]^T ----
        {
            float acc[4][4];
            #pragma unroll
            for (int gg = 0; gg < 4; gg++) {
                int col = wn * 32 + gg * 8 + col0;
                float ba = smf[SM_B1f / 4 + col], bb = smf[SM_B1f / 4 + col + 1];
                acc[gg][0] = ba; acc[gg][1] = bb; acc[gg][2] = ba; acc[gg][3] = bb;
            }
            #pragma unroll
            for (int p = 0; p < 3; p++) {
                uint32_t bA = sb + ((p == 2) ? SM_AL : SM_AH);
                uint32_t bB = sb + ((p == 1) ? SM_W1L : SM_W1H);
                #pragma unroll
                for (int kk = 0; kk < IN_DIM; kk += 16) {
                    uint32_t a[4], bq0[4], bq1[4];
                    ldsm4(a, bA + (uint32_t)((wm*16 + arow) * 72 + kk + acol8) * 2);
                    uint32_t ab = bB + (uint32_t)((wn*32 + brow) * 72 + kk + bcol8) * 2;
                    ldsm4(bq0, ab);
                    ldsm4(bq1, ab + 16 * 72 * 2);
                    mma16816(acc[0], a, bq0);
                    mma16816(acc[1], a, bq0 + 2);
                    mma16816(acc[2], a, bq1);
                    mma16816(acc[3], a, bq1 + 2);
                }
            }
            #pragma unroll
            for (int gg = 0; gg < 4; gg++) {
                int col = wn * 32 + gg * 8 + col0;
                #pragma unroll
                for (int half = 0; half < 2; half++) {
                    float v0 = fmaxf(acc[gg][2*half],     0.f);
                    float v1 = fmaxf(acc[gg][2*half + 1], 0.f);
                    uint32_t h2 = pack_bf16(v0, v1);
                    float h0 = __uint_as_float(h2 << 16);
                    float h1 = __uint_as_float(h2 & 0xFFFF0000u);
                    uint32_t l2 = pack_bf16(v0 - h0, v1 - h1);
                    int r = wm * 16 + row0 + half * 8;
                    uint32_t off = (uint32_t)(r * 136 + col) * 2;
                    *reinterpret_cast<uint32_t*>(smem + SM_TH + off) = h2;
                    *reinterpret_cast<uint32_t*>(smem + SM_TL + off) = l2;
                }
            }
        }
        __syncthreads();

        // ---- layer 2: 64x128 = T[64x128] @ W2t[128x128]^T ----
        {
            float acc[4][4];
            #pragma unroll
            for (int gg = 0; gg < 4; gg++) {
                int col = wn * 32 + gg * 8 + col0;
                float ba = smf[SM_B2f / 4 + col], bb = smf[SM_B2f / 4 + col + 1];
                acc[gg][0] = ba; acc[gg][1] = bb; acc[gg][2] = ba; acc[gg][3] = bb;
            }
            #pragma unroll
            for (int p = 0; p < 3; p++) {
                uint32_t bA = sb + ((p == 2) ? SM_TL : SM_TH);
                uint32_t bB = sb + ((p == 1) ? SM_W2L : SM_W2H);
                #pragma unroll
                for (int kk = 0; kk < HID_DIM; kk += 16) {
                    uint32_t a[4], bq0[4], bq1[4];
                    ldsm4(a, bA + (uint32_t)((wm*16 + arow) * 136 + kk + acol8) * 2);
                    uint32_t ab = bB + (uint32_t)((wn*32 + brow) * 136 + kk + bcol8) * 2;
                    ldsm4(bq0, ab);
                    ldsm4(bq1, ab + 16 * 136 * 2);
                    mma16816(acc[0], a, bq0);
                    mma16816(acc[1], a, bq0 + 2);
                    mma16816(acc[2], a, bq1);
                    mma16816(acc[3], a, bq1 + 2);
                }
            }
            #pragma unroll
            for (int gg = 0; gg < 4; gg++) {
                int col = wn * 32 + gg * 8 + col0;
                #pragma unroll
                for (int half = 0; half < 2; half++) {
                    float v0 = fmaxf(acc[gg][2*half],     0.f);
                    float v1 = fmaxf(acc[gg][2*half + 1], 0.f);
                    uint32_t h2 = pack_bf16(v0, v1);
                    float h0 = __uint_as_float(h2 << 16);
                    float h1 = __uint_as_float(h2 & 0xFFFF0000u);
                    uint32_t l2 = pack_bf16(v0 - h0, v1 - h1);
                    int r = wm * 16 + row0 + half * 8;
                    uint32_t off = (uint32_t)(r * 136 + col) * 2;
                    *reinterpret_cast<uint32_t*>(smem + SM_HH + off) = h2;
                    *reinterpret_cast<uint32_t*>(smem + SM_HL + off) = l2;
                }
            }
        }
        __syncthreads();

        // ---- layer 3: 64x64(pad) = H[64x128] @ W3t[64x128]^T -> g_t --------
        {
            float acc[2][4];
            #pragma unroll
            for (int gg = 0; gg < 2; gg++) {
                acc[gg][0] = 0.f; acc[gg][1] = 0.f; acc[gg][2] = 0.f; acc[gg][3] = 0.f;
            }
            #pragma unroll
            for (int p = 0; p < 3; p++) {
                uint32_t bA = sb + ((p == 2) ? SM_HL : SM_HH);
                uint32_t bB = sb + ((p == 1) ? SM_W3L : SM_W3H);
                #pragma unroll
                for (int kk = 0; kk < HID_DIM; kk += 16) {
                    uint32_t a[4], bq0[4];
                    ldsm4(a, bA + (uint32_t)((wm*16 + arow) * 136 + kk + acol8) * 2);
                    ldsm4(bq0, bB + (uint32_t)((wn*16 + brow) * 136 + kk + bcol8) * 2);
                    mma16816(acc[0], a, bq0);
                    mma16816(acc[1], a, bq0 + 2);
                }
            }
            #pragma unroll
            for (int gg = 0; gg < 2; gg++) {
                int col = wn * 16 + gg * 8 + col0;
                if (col < OUT_DIM) {
                    #pragma unroll
                    for (int half = 0; half < 2; half++) {
                        int node = base + wm * 16 + row0 + half * 8;
                        if (node < N_NODES) {
                            float2 v = make_float2(acc[gg][2*half], acc[gg][2*half+1]);
                            *reinterpret_cast<float2*>(
                                g_t + (size_t)node * OUT_DIM + col) = v;
                        }
                    }
                }
            }
        }
        __syncthreads();   // H consumed before next tile's A staging (alias)
    }
}

// ---------------- K-final2: gather2 + bias + relu + log_softmax -------------
__global__ void k_final2(const float* __restrict__ b3, float* __restrict__ out) {
    int w = (blockIdx.x * blockDim.x + threadIdx.x) >> 5;
    if (w >= N_NODES) return;
    int lane = threadIdx.x & 31;
    int p = lane / 10;
    int c = lane - p * 10;
    bool active = p < 3;
    int deg = min(g_deg[w], CAP);
    const int* row = g_csr + (size_t)w * CAP;

    float4 acc = make_float4(0.f, 0.f, 0.f, 0.f);
    if (p == 0)
        acc = *reinterpret_cast<const float4*>(g_t + (size_t)w * OUT_DIM + c * 4);

    #pragma unroll 3
    for (int j = 0; j < deg; j += 3) {
        if (active && j + p < deg) {
            int s = row[j + p];
            float4 v = *reinterpret_cast<const float4*>(
                g_t + (size_t)s * OUT_DIM + c * 4);
            acc.x += v.x; acc.y += v.y; acc.z += v.z; acc.w += v.w;
        }
    }

    float4 u;
    u.x = acc.x + __shfl_sync(0xffffffffu, acc.x, lane + 10)
                + __shfl_sync(0xffffffffu, acc.x, lane + 20);
    u.y = acc.y + __shfl_sync(0xffffffffu, acc.y, lane + 10)
                + __shfl_sync(0xffffffffu, acc.y, lane + 20);
    u.z = acc.z + __shfl_sync(0xffffffffu, acc.z, lane + 10)
                + __shfl_sync(0xffffffffu, acc.z, lane + 20);
    u.w = acc.w + __shfl_sync(0xffffffffu, acc.w, lane + 10)
                + __shfl_sync(0xffffffffu, acc.w, lane + 20);

    bool owner = lane < 10;
    float4 a = make_float4(-3.4e38f, -3.4e38f, -3.4e38f, -3.4e38f);
    if (owner) {
        float4 bv = *reinterpret_cast<const float4*>(b3 + c * 4);
        a.x = fmaxf(u.x + bv.x, 0.f);
        a.y = fmaxf(u.y + bv.y, 0.f);
        a.z = fmaxf(u.z + bv.z, 0.f);
        a.w = fmaxf(u.w + bv.w, 0.f);
    }

    float m = fmaxf(fmaxf(a.x, a.y), fmaxf(a.z, a.w));
    #pragma unroll
    for (int o = 16; o > 0; o >>= 1)
        m = fmaxf(m, __shfl_xor_sync(0xffffffffu, m, o));

    float s = owner ? (expf(a.x - m) + expf(a.y - m) +
                       expf(a.z - m) + expf(a.w - m)) : 0.f;
    #pragma unroll
    for (int o = 16; o > 0; o >>= 1)
        s += __shfl_xor_sync(0xffffffffu, s, o);

    float lse = m + logf(s);
    if (owner) {
        float4 r = make_float4(a.x - lse, a.y - lse, a.z - lse, a.w - lse);
        *reinterpret_cast<float4*>(out + (size_t)w * OUT_DIM + c * 4) = r;
    }
}

// ---------------- launch ----------------
extern "C" void kernel_launch(void* const* d_in, const int* in_sizes, int n_in,
                              void* d_out, int out_size) {
    const float* x  = (const float*)d_in[0];
    const void*  ei = d_in[1];
    const float* W1 = (const float*)d_in[2];
    const float* b1 = (const float*)d_in[3];
    const float* W2 = (const float*)d_in[4];
    const float* b2 = (const float*)d_in[5];
    const float* W3 = (const float*)d_in[6];
    const float* b3 = (const float*)d_in[7];
    float* out = (float*)d_out;

    static bool attr_set = false;
    if (!attr_set) {
        cudaFuncSetAttribute(k_mlp, cudaFuncAttributeMaxDynamicSharedMemorySize,
                             SMEM_MLP);
        attr_set = true;
    }

    k_prep<<<(N_NODES + 255) / 256, 256>>>((const long long*)ei);
    k_build<<<(N_EDGES + 255) / 256, 256>>>(ei);
    k_gather1<<<(N_NODES * 32 + 255) / 256, 256>>>(x);
    k_mlp<<<148, 512, SMEM_MLP>>>(W1, b1, W2, b2, W3);
    k_final2<<<(N_NODES * 32 + 255) / 256, 256>>>(b3, out);
}